// round 2
// baseline (speedup 1.0000x reference)
#include <cuda_runtime.h>
#include <cstdint>

#define NODES_MAX 100000

// ---------------- device scratch (static, allocation-free) ----------------
__device__ float g_H[(size_t)NODES_MAX * 128];     // pre-aggregation h = (x*out_norm)@W
__device__ float g_AGG[(size_t)NODES_MAX * 128];   // aggregation accumulator (128-wide layers)
__device__ float g_AGG2[(size_t)NODES_MAX * 64];   // aggregation accumulator (64-wide layer 3)
__device__ float g_out_norm[NODES_MAX];
__device__ float g_in_norm[NODES_MAX];
__device__ int   g_odeg[NODES_MAX];
__device__ int   g_ideg[NODES_MAX];

// ---------------- degree / norm kernels ----------------
__global__ void k_init_deg(int n) {
    int i = blockIdx.x * blockDim.x + threadIdx.x;
    if (i < n) { g_odeg[i] = 1; g_ideg[i] = 1; }   // self-loop contributes 1 to each
}

__global__ void k_count_deg(const int* __restrict__ src, const int* __restrict__ dst, int E) {
    int i = blockIdx.x * blockDim.x + threadIdx.x;
    int st = gridDim.x * blockDim.x;
    for (; i < E; i += st) {
        atomicAdd(&g_odeg[src[i]], 1);
        atomicAdd(&g_ideg[dst[i]], 1);
    }
}

__global__ void k_norms(int n) {
    int i = blockIdx.x * blockDim.x + threadIdx.x;
    if (i < n) {
        g_out_norm[i] = rsqrtf((float)g_odeg[i]);
        g_in_norm[i]  = rsqrtf((float)g_ideg[i]);
    }
}

// ---------------- fused GEMM ----------------
// Computes H = X_eff @ W where
//   MODE 0: X_eff[r][k] = X[r][k] * out_norm[r]                      (layer 1, X = feat)
//   MODE 1: X_eff[r][k] = relu(g_AGG[r][k]*in_norm[r] + bprev[k]) * out_norm[r]
// Writes the result to BOTH the gather buffer (H) and the aggregation
// accumulator (AGG / AGG2) — the latter pre-loads the self-loop message.
template <int DOUT, int MODE>
__global__ void __launch_bounds__(256)
k_gemm(const float* __restrict__ X, const float* __restrict__ W,
       const float* __restrict__ bprev, int n)
{
    constexpr int CG   = DOUT / 4;    // float4 column groups
    constexpr int TY   = 256 / CG;    // row groups
    constexpr int ROWS = TY * 8;      // rows per block tile
    constexpr int XSS  = 136;         // xs row stride (floats), 16B-aligned, bank-rotating

    extern __shared__ float sm[];
    float* ws = sm;                   // [128][DOUT]
    float* xs = sm + 128 * DOUT;      // [ROWS][XSS]

    const int t    = threadIdx.x;
    const int row0 = blockIdx.x * ROWS;

    // stage W: ALL 128 K-rows x CG float4 column groups
    {
        const float4* W4  = (const float4*)W;
        float4*       ws4 = (float4*)ws;
        for (int i = t; i < 128 * CG; i += 256) ws4[i] = W4[i];
    }

    // stage X tile (epilogue of previous layer fused here)
    for (int i = t; i < ROWS * 32; i += 256) {
        int r  = i >> 5;
        int k4 = i & 31;
        int row = row0 + r;
        float4 v = make_float4(0.f, 0.f, 0.f, 0.f);
        if (row < n) {
            if (MODE == 0) {
                float on = g_out_norm[row];
                v = ((const float4*)X)[(size_t)row * 32 + k4];
                v.x *= on; v.y *= on; v.z *= on; v.w *= on;
            } else {
                float inn = g_in_norm[row];
                float on  = g_out_norm[row];
                float4 a  = ((const float4*)g_AGG)[(size_t)row * 32 + k4];
                float4 bb = ((const float4*)bprev)[k4];
                v.x = fmaxf(fmaf(a.x, inn, bb.x), 0.f) * on;
                v.y = fmaxf(fmaf(a.y, inn, bb.y), 0.f) * on;
                v.z = fmaxf(fmaf(a.z, inn, bb.z), 0.f) * on;
                v.w = fmaxf(fmaf(a.w, inn, bb.w), 0.f) * on;
            }
        }
        float* p = &xs[r * XSS + (k4 << 2)];
        p[0] = v.x; p[1] = v.y; p[2] = v.z; p[3] = v.w;
    }
    __syncthreads();

    const int tx = t % CG;
    const int ty = t / CG;
    float acc[8][4];
#pragma unroll
    for (int r = 0; r < 8; r++) { acc[r][0] = acc[r][1] = acc[r][2] = acc[r][3] = 0.f; }

    const float*  xrow = xs + ty * 8 * XSS;
    const float4* ws4  = (const float4*)ws;

#pragma unroll 4
    for (int k4 = 0; k4 < 32; k4++) {
        float4 w0 = ws4[(k4 * 4 + 0) * CG + tx];
        float4 w1 = ws4[(k4 * 4 + 1) * CG + tx];
        float4 w2 = ws4[(k4 * 4 + 2) * CG + tx];
        float4 w3 = ws4[(k4 * 4 + 3) * CG + tx];
#pragma unroll
        for (int r = 0; r < 8; r++) {
            float4 xv = *(const float4*)&xrow[r * XSS + k4 * 4];
            acc[r][0] = fmaf(xv.x, w0.x, acc[r][0]);
            acc[r][1] = fmaf(xv.x, w0.y, acc[r][1]);
            acc[r][2] = fmaf(xv.x, w0.z, acc[r][2]);
            acc[r][3] = fmaf(xv.x, w0.w, acc[r][3]);
            acc[r][0] = fmaf(xv.y, w1.x, acc[r][0]);
            acc[r][1] = fmaf(xv.y, w1.y, acc[r][1]);
            acc[r][2] = fmaf(xv.y, w1.z, acc[r][2]);
            acc[r][3] = fmaf(xv.y, w1.w, acc[r][3]);
            acc[r][0] = fmaf(xv.z, w2.x, acc[r][0]);
            acc[r][1] = fmaf(xv.z, w2.y, acc[r][1]);
            acc[r][2] = fmaf(xv.z, w2.z, acc[r][2]);
            acc[r][3] = fmaf(xv.z, w2.w, acc[r][3]);
            acc[r][0] = fmaf(xv.w, w3.x, acc[r][0]);
            acc[r][1] = fmaf(xv.w, w3.y, acc[r][1]);
            acc[r][2] = fmaf(xv.w, w3.z, acc[r][2]);
            acc[r][3] = fmaf(xv.w, w3.w, acc[r][3]);
        }
    }

    float* Hd = g_H;
    float* Ad = (DOUT == 128) ? g_AGG : g_AGG2;
#pragma unroll
    for (int r = 0; r < 8; r++) {
        int row = row0 + ty * 8 + r;
        if (row < n) {
            float4 v = make_float4(acc[r][0], acc[r][1], acc[r][2], acc[r][3]);
            size_t off = (size_t)row * CG + tx;
            ((float4*)Hd)[off] = v;
            ((float4*)Ad)[off] = v;
        }
    }
}

// ---------------- edge aggregation (vector atomics) ----------------
__device__ __forceinline__ void red_add_v4(float4* addr, float4 v) {
    asm volatile("red.global.add.v4.f32 [%0], {%1,%2,%3,%4};"
                 :: "l"(addr), "f"(v.x), "f"(v.y), "f"(v.z), "f"(v.w)
                 : "memory");
}

// 128-wide: one warp per edge, lane handles one float4 of the 128-float row
__global__ void k_edge128(const int* __restrict__ src, const int* __restrict__ dst, int E) {
    int gtid = blockIdx.x * blockDim.x + threadIdx.x;
    int lane = gtid & 31;
    int w    = gtid >> 5;
    int nw   = (gridDim.x * blockDim.x) >> 5;
    for (int e = w; e < E; e += nw) {
        int s = __ldg(&src[e]);
        int d = __ldg(&dst[e]);
        float4 v = ((const float4*)g_H)[(size_t)s * 32 + lane];
        red_add_v4(&((float4*)g_AGG)[(size_t)d * 32 + lane], v);
    }
}

// 64-wide: half-warp per edge (16 float4 per row)
__global__ void k_edge64(const int* __restrict__ src, const int* __restrict__ dst, int E) {
    int gtid = blockIdx.x * blockDim.x + threadIdx.x;
    int lane = gtid & 31;
    int w    = gtid >> 5;
    int nw   = (gridDim.x * blockDim.x) >> 5;
    int sub  = lane >> 4;    // which edge of the pair
    int l16  = lane & 15;    // float4 index within row
    for (int e0 = w * 2; e0 < E; e0 += nw * 2) {
        int e = e0 + sub;
        if (e < E) {
            int s = __ldg(&src[e]);
            int d = __ldg(&dst[e]);
            float4 v = ((const float4*)g_H)[(size_t)s * 16 + l16];
            red_add_v4(&((float4*)g_AGG2)[(size_t)d * 16 + l16], v);
        }
    }
}

// ---------------- final epilogue: out = AGG2*in_norm + b3 ----------------
__global__ void k_final(const float* __restrict__ b3, float* __restrict__ out, int n) {
    int i = blockIdx.x * blockDim.x + threadIdx.x;   // over n*16 float4s
    if (i < n * 16) {
        int row = i >> 4;
        int c4  = i & 15;
        float4 a  = ((const float4*)g_AGG2)[i];
        float4 bb = ((const float4*)b3)[c4];
        float inn = g_in_norm[row];
        float4 o;
        o.x = fmaf(a.x, inn, bb.x);
        o.y = fmaf(a.y, inn, bb.y);
        o.z = fmaf(a.z, inn, bb.z);
        o.w = fmaf(a.w, inn, bb.w);
        ((float4*)out)[i] = o;
    }
}

// ---------------- launcher ----------------
extern "C" void kernel_launch(void* const* d_in, const int* in_sizes, int n_in,
                              void* d_out, int out_size)
{
    const float* feat = (const float*)d_in[0];
    const int*   src  = (const int*)d_in[1];
    const int*   dst  = (const int*)d_in[2];
    const float* W1   = (const float*)d_in[3];
    const float* b1   = (const float*)d_in[4];
    const float* W2   = (const float*)d_in[5];
    const float* b2   = (const float*)d_in[6];
    const float* W3   = (const float*)d_in[7];
    const float* b3   = (const float*)d_in[8];
    float*       out  = (float*)d_out;

    const int n = in_sizes[0] / 128;   // 100000
    const int E = in_sizes[1];         // 1600000

    const int smem128 = (128 * 128 + 64 * 136) * (int)sizeof(float);   // ~100 KB
    const int smem64  = (128 * 64 + 128 * 136) * (int)sizeof(float);   // ~100 KB
    cudaFuncSetAttribute((const void*)k_gemm<128, 0>,
                         cudaFuncAttributeMaxDynamicSharedMemorySize, smem128);
    cudaFuncSetAttribute((const void*)k_gemm<128, 1>,
                         cudaFuncAttributeMaxDynamicSharedMemorySize, smem128);
    cudaFuncSetAttribute((const void*)k_gemm<64, 1>,
                         cudaFuncAttributeMaxDynamicSharedMemorySize, smem64);

    // degrees + norms (include self-loop via init=1)
    k_init_deg<<<(n + 255) / 256, 256>>>(n);
    k_count_deg<<<1024, 256>>>(src, dst, E);
    k_norms<<<(n + 255) / 256, 256>>>(n);

    // layer 1: h1 = (feat*out_norm)@W1 ; agg1 = h1(self) + scatter
    k_gemm<128, 0><<<(n + 63) / 64, 256, smem128>>>(feat, W1, nullptr, n);
    k_edge128<<<2048, 256>>>(src, dst, E);

    // layer 2: x2 = relu(agg1*in_norm + b1); h2 = (x2*out_norm)@W2 ; aggregate
    k_gemm<128, 1><<<(n + 63) / 64, 256, smem128>>>(nullptr, W2, b1, n);
    k_edge128<<<2048, 256>>>(src, dst, E);

    // layer 3: x3 = relu(agg2*in_norm + b2); h3 = (x3*out_norm)@W3 ; aggregate (64-wide)
    k_gemm<64, 1><<<(n + 127) / 128, 256, smem64>>>(nullptr, W3, b2, n);
    k_edge64<<<2048, 256>>>(src, dst, E);

    // out = agg3*in_norm + b3
    k_final<<<(n * 16 + 255) / 256, 256>>>(b3, out, n);
}

// round 3
// speedup vs baseline: 1.1762x; 1.1762x over previous
#include <cuda_runtime.h>
#include <cstdint>

#define NODES_MAX 100000
#define E_MAX     1600000

// ---------------- device scratch (static, allocation-free) ----------------
__device__ float g_H[(size_t)NODES_MAX * 128];     // pre-aggregation h = (x*out_norm)@W
__device__ float g_AGG[(size_t)NODES_MAX * 128];   // aggregation result (128-wide layers)
__device__ float g_out_norm[NODES_MAX];
__device__ float g_in_norm[NODES_MAX];
__device__ int   g_odeg[NODES_MAX];
__device__ int   g_ideg[NODES_MAX];
__device__ int   g_row_ptr[NODES_MAX + 1];         // CSR offsets (dst-grouped)
__device__ int   g_fill[NODES_MAX];                // scatter cursors
__device__ int   g_csr_src[E_MAX];                 // src ids grouped by dst

// ---------------- degree / norm ----------------
__global__ void k_init_deg(int n) {
    int i = blockIdx.x * blockDim.x + threadIdx.x;
    if (i < n) { g_odeg[i] = 1; g_ideg[i] = 1; }   // self-loop contributes 1 to each
}

__global__ void k_count_deg(const int* __restrict__ src, const int* __restrict__ dst, int E) {
    int i = blockIdx.x * blockDim.x + threadIdx.x;
    int st = gridDim.x * blockDim.x;
    for (; i < E; i += st) {
        atomicAdd(&g_odeg[src[i]], 1);
        atomicAdd(&g_ideg[dst[i]], 1);
    }
}

__global__ void k_norms(int n) {
    int i = blockIdx.x * blockDim.x + threadIdx.x;
    if (i < n) {
        g_out_norm[i] = rsqrtf((float)g_odeg[i]);
        g_in_norm[i]  = rsqrtf((float)g_ideg[i]);
    }
}

// ---------------- CSR build: scan + scatter ----------------
// Exclusive scan of (ideg[i]-1) = per-dst real-edge count. Single 1024-thread block.
__global__ void k_scan(int n) {
    __shared__ int part[1024];
    int t = threadIdx.x;
    int chunk = (n + 1023) / 1024;
    int lo = t * chunk;
    int hi = min(lo + chunk, n);
    int s = 0;
    for (int i = lo; i < hi; i++) s += g_ideg[i] - 1;
    part[t] = s;
    __syncthreads();
    // Hillis-Steele inclusive scan
    for (int off = 1; off < 1024; off <<= 1) {
        int v = (t >= off) ? part[t - off] : 0;
        __syncthreads();
        part[t] += v;
        __syncthreads();
    }
    int base = (t == 0) ? 0 : part[t - 1];
    for (int i = lo; i < hi; i++) {
        g_row_ptr[i] = base;
        g_fill[i]    = base;
        base += g_ideg[i] - 1;
    }
    if (t == 1023) g_row_ptr[n] = base;   // == E
}

__global__ void k_scatter(const int* __restrict__ src, const int* __restrict__ dst, int E) {
    int i = blockIdx.x * blockDim.x + threadIdx.x;
    int st = gridDim.x * blockDim.x;
    for (; i < E; i += st) {
        int d = dst[i];
        int pos = atomicAdd(&g_fill[d], 1);
        g_csr_src[pos] = src[i];
    }
}

// ---------------- fused GEMM ----------------
//   MODE 0: X_eff[r][k] = X[r][k] * out_norm[r]                      (layer 1, X = feat)
//   MODE 1: X_eff[r][k] = relu(g_AGG[r][k]*in_norm[r] + bprev[k]) * out_norm[r]
// Writes H only (self-loop handled in the aggregator's accumulator init).
template <int DOUT, int MODE>
__global__ void __launch_bounds__(256)
k_gemm(const float* __restrict__ X, const float* __restrict__ W,
       const float* __restrict__ bprev, int n)
{
    constexpr int CG   = DOUT / 4;    // float4 column groups
    constexpr int TY   = 256 / CG;    // row groups
    constexpr int ROWS = TY * 8;      // rows per block tile
    constexpr int XSS  = 136;         // xs row stride (floats)

    extern __shared__ float sm[];
    float* ws = sm;                   // [128][DOUT]
    float* xs = sm + 128 * DOUT;      // [ROWS][XSS]

    const int t    = threadIdx.x;
    const int row0 = blockIdx.x * ROWS;

    // stage W: all 128 K-rows x CG float4 column groups
    {
        const float4* W4  = (const float4*)W;
        float4*       ws4 = (float4*)ws;
        for (int i = t; i < 128 * CG; i += 256) ws4[i] = W4[i];
    }

    // stage X tile (previous layer's epilogue fused here)
    for (int i = t; i < ROWS * 32; i += 256) {
        int r  = i >> 5;
        int k4 = i & 31;
        int row = row0 + r;
        float4 v = make_float4(0.f, 0.f, 0.f, 0.f);
        if (row < n) {
            if (MODE == 0) {
                float on = g_out_norm[row];
                v = ((const float4*)X)[(size_t)row * 32 + k4];
                v.x *= on; v.y *= on; v.z *= on; v.w *= on;
            } else {
                float inn = g_in_norm[row];
                float on  = g_out_norm[row];
                float4 a  = ((const float4*)g_AGG)[(size_t)row * 32 + k4];
                float4 bb = ((const float4*)bprev)[k4];
                v.x = fmaxf(fmaf(a.x, inn, bb.x), 0.f) * on;
                v.y = fmaxf(fmaf(a.y, inn, bb.y), 0.f) * on;
                v.z = fmaxf(fmaf(a.z, inn, bb.z), 0.f) * on;
                v.w = fmaxf(fmaf(a.w, inn, bb.w), 0.f) * on;
            }
        }
        float* p = &xs[r * XSS + (k4 << 2)];
        p[0] = v.x; p[1] = v.y; p[2] = v.z; p[3] = v.w;
    }
    __syncthreads();

    const int tx = t % CG;
    const int ty = t / CG;
    float acc[8][4];
#pragma unroll
    for (int r = 0; r < 8; r++) { acc[r][0] = acc[r][1] = acc[r][2] = acc[r][3] = 0.f; }

    const float*  xrow = xs + ty * 8 * XSS;
    const float4* ws4  = (const float4*)ws;

#pragma unroll 4
    for (int k4 = 0; k4 < 32; k4++) {
        float4 w0 = ws4[(k4 * 4 + 0) * CG + tx];
        float4 w1 = ws4[(k4 * 4 + 1) * CG + tx];
        float4 w2 = ws4[(k4 * 4 + 2) * CG + tx];
        float4 w3 = ws4[(k4 * 4 + 3) * CG + tx];
#pragma unroll
        for (int r = 0; r < 8; r++) {
            float4 xv = *(const float4*)&xrow[r * XSS + k4 * 4];
            acc[r][0] = fmaf(xv.x, w0.x, acc[r][0]);
            acc[r][1] = fmaf(xv.x, w0.y, acc[r][1]);
            acc[r][2] = fmaf(xv.x, w0.z, acc[r][2]);
            acc[r][3] = fmaf(xv.x, w0.w, acc[r][3]);
            acc[r][0] = fmaf(xv.y, w1.x, acc[r][0]);
            acc[r][1] = fmaf(xv.y, w1.y, acc[r][1]);
            acc[r][2] = fmaf(xv.y, w1.z, acc[r][2]);
            acc[r][3] = fmaf(xv.y, w1.w, acc[r][3]);
            acc[r][0] = fmaf(xv.z, w2.x, acc[r][0]);
            acc[r][1] = fmaf(xv.z, w2.y, acc[r][1]);
            acc[r][2] = fmaf(xv.z, w2.z, acc[r][2]);
            acc[r][3] = fmaf(xv.z, w2.w, acc[r][3]);
            acc[r][0] = fmaf(xv.w, w3.x, acc[r][0]);
            acc[r][1] = fmaf(xv.w, w3.y, acc[r][1]);
            acc[r][2] = fmaf(xv.w, w3.z, acc[r][2]);
            acc[r][3] = fmaf(xv.w, w3.w, acc[r][3]);
        }
    }

#pragma unroll
    for (int r = 0; r < 8; r++) {
        int row = row0 + ty * 8 + r;
        if (row < n) {
            float4 v = make_float4(acc[r][0], acc[r][1], acc[r][2], acc[r][3]);
            ((float4*)g_H)[(size_t)row * CG + tx] = v;
        }
    }
}

// ---------------- CSR gather-reduce aggregation ----------------
// 128-wide: one warp per dst node; acc initialized with self-loop message H[dst].
__global__ void __launch_bounds__(256)
k_agg128(int n) {
    int w    = (blockIdx.x * blockDim.x + threadIdx.x) >> 5;
    int lane = threadIdx.x & 31;
    if (w >= n) return;
    const float4* H4 = (const float4*)g_H;
    int beg = g_row_ptr[w];
    int end = g_row_ptr[w + 1];
    float4 acc = H4[(size_t)w * 32 + lane];   // self-loop
    int j = beg;
    for (; j + 1 < end; j += 2) {
        int s0 = __ldg(&g_csr_src[j]);
        int s1 = __ldg(&g_csr_src[j + 1]);
        float4 v0 = H4[(size_t)s0 * 32 + lane];
        float4 v1 = H4[(size_t)s1 * 32 + lane];
        acc.x += v0.x; acc.y += v0.y; acc.z += v0.z; acc.w += v0.w;
        acc.x += v1.x; acc.y += v1.y; acc.z += v1.z; acc.w += v1.w;
    }
    if (j < end) {
        int s0 = __ldg(&g_csr_src[j]);
        float4 v0 = H4[(size_t)s0 * 32 + lane];
        acc.x += v0.x; acc.y += v0.y; acc.z += v0.z; acc.w += v0.w;
    }
    ((float4*)g_AGG)[(size_t)w * 32 + lane] = acc;
}

// 64-wide, final layer: half-warp per dst node; fuses out = acc*in_norm + b3.
__global__ void __launch_bounds__(256)
k_agg64_final(const float* __restrict__ b3, float* __restrict__ out, int n) {
    int gt   = blockIdx.x * blockDim.x + threadIdx.x;
    int lane = gt & 31;
    int w    = gt >> 5;
    int sub  = lane >> 4;
    int l16  = lane & 15;
    int node = w * 2 + sub;
    if (node >= n) return;
    const float4* H4 = (const float4*)g_H;
    int beg = g_row_ptr[node];
    int end = g_row_ptr[node + 1];
    float4 acc = H4[(size_t)node * 16 + l16];  // self-loop
    int j = beg;
    for (; j + 1 < end; j += 2) {
        int s0 = __ldg(&g_csr_src[j]);
        int s1 = __ldg(&g_csr_src[j + 1]);
        float4 v0 = H4[(size_t)s0 * 16 + l16];
        float4 v1 = H4[(size_t)s1 * 16 + l16];
        acc.x += v0.x; acc.y += v0.y; acc.z += v0.z; acc.w += v0.w;
        acc.x += v1.x; acc.y += v1.y; acc.z += v1.z; acc.w += v1.w;
    }
    if (j < end) {
        int s0 = __ldg(&g_csr_src[j]);
        float4 v0 = H4[(size_t)s0 * 16 + l16];
        acc.x += v0.x; acc.y += v0.y; acc.z += v0.z; acc.w += v0.w;
    }
    float inn = g_in_norm[node];
    float4 bb = ((const float4*)b3)[l16];
    float4 o;
    o.x = fmaf(acc.x, inn, bb.x);
    o.y = fmaf(acc.y, inn, bb.y);
    o.z = fmaf(acc.z, inn, bb.z);
    o.w = fmaf(acc.w, inn, bb.w);
    ((float4*)out)[(size_t)node * 16 + l16] = o;
}

// ---------------- launcher ----------------
extern "C" void kernel_launch(void* const* d_in, const int* in_sizes, int n_in,
                              void* d_out, int out_size)
{
    const float* feat = (const float*)d_in[0];
    const int*   src  = (const int*)d_in[1];
    const int*   dst  = (const int*)d_in[2];
    const float* W1   = (const float*)d_in[3];
    const float* b1   = (const float*)d_in[4];
    const float* W2   = (const float*)d_in[5];
    const float* b2   = (const float*)d_in[6];
    const float* W3   = (const float*)d_in[7];
    const float* b3   = (const float*)d_in[8];
    float*       out  = (float*)d_out;

    const int n = in_sizes[0] / 128;   // 100000
    const int E = in_sizes[1];         // 1600000

    const int smem128 = (128 * 128 + 64 * 136) * (int)sizeof(float);
    const int smem64  = (128 * 64 + 128 * 136) * (int)sizeof(float);
    cudaFuncSetAttribute((const void*)k_gemm<128, 0>,
                         cudaFuncAttributeMaxDynamicSharedMemorySize, smem128);
    cudaFuncSetAttribute((const void*)k_gemm<128, 1>,
                         cudaFuncAttributeMaxDynamicSharedMemorySize, smem128);
    cudaFuncSetAttribute((const void*)k_gemm<64, 1>,
                         cudaFuncAttributeMaxDynamicSharedMemorySize, smem64);

    // degrees + norms (self-loop via init=1)
    k_init_deg<<<(n + 255) / 256, 256>>>(n);
    k_count_deg<<<1024, 256>>>(src, dst, E);
    k_norms<<<(n + 255) / 256, 256>>>(n);

    // CSR build (reused by all 3 layers)
    k_scan<<<1, 1024>>>(n);
    k_scatter<<<1024, 256>>>(src, dst, E);

    // layer 1
    k_gemm<128, 0><<<(n + 63) / 64, 256, smem128>>>(feat, W1, nullptr, n);
    k_agg128<<<(n * 32 + 255) / 256, 256>>>(n);

    // layer 2
    k_gemm<128, 1><<<(n + 63) / 64, 256, smem128>>>(nullptr, W2, b1, n);
    k_agg128<<<(n * 32 + 255) / 256, 256>>>(n);

    // layer 3 (64-wide) + fused final epilogue straight to d_out
    k_gemm<64, 1><<<(n + 127) / 128, 256, smem64>>>(nullptr, W3, b2, n);
    k_agg64_final<<<(n * 16 + 255) / 256, 256>>>(b3, out, n);
}

// round 4
// speedup vs baseline: 1.5847x; 1.3473x over previous
#include <cuda_runtime.h>
#include <cstdint>

#define NODES_MAX 100000
#define E_MAX     1600000

// ---------------- device scratch (static, allocation-free) ----------------
__device__ float g_H[(size_t)NODES_MAX * 128];     // pre-aggregation h = (x*out_norm)@W
__device__ float g_AGG[(size_t)NODES_MAX * 128];   // aggregation result (128-wide layers)
__device__ float g_out_norm[NODES_MAX];
__device__ float g_in_norm[NODES_MAX];
__device__ int   g_odeg[NODES_MAX];
__device__ int   g_ideg[NODES_MAX];
__device__ int   g_row_beg[NODES_MAX];             // CSR segment start per dst node
__device__ int   g_fill[NODES_MAX];                // scatter cursors
__device__ int   g_csr_src[E_MAX];                 // src ids grouped by dst
__device__ int   g_alloc_ctr;                      // segment allocation cursor

// ---------------- degree / norm ----------------
__global__ void k_init_deg(int n) {
    int i = blockIdx.x * blockDim.x + threadIdx.x;
    if (i < n) { g_odeg[i] = 1; g_ideg[i] = 1; }   // self-loop contributes 1 to each
    if (i == 0) g_alloc_ctr = 0;
}

__global__ void k_count_deg(const int* __restrict__ src, const int* __restrict__ dst, int E) {
    int i = blockIdx.x * blockDim.x + threadIdx.x;
    int st = gridDim.x * blockDim.x;
    for (; i < E; i += st) {
        atomicAdd(&g_odeg[src[i]], 1);
        atomicAdd(&g_ideg[dst[i]], 1);
    }
}

__global__ void k_norms(int n) {
    int i = blockIdx.x * blockDim.x + threadIdx.x;
    if (i < n) {
        g_out_norm[i] = rsqrtf((float)g_odeg[i]);
        g_in_norm[i]  = rsqrtf((float)g_ideg[i]);
    }
}

// ---------------- CSR segment allocation (order-free, fully parallel) ----------------
// Each block: in-block exclusive scan of per-node real-edge counts, one atomicAdd
// per block on the global cursor. Segment ORDER is irrelevant to the aggregators.
__global__ void __launch_bounds__(256)
k_alloc(int n) {
    __shared__ int warp_sums[8];
    __shared__ int block_base;
    int i    = blockIdx.x * 256 + threadIdx.x;
    int lane = threadIdx.x & 31;
    int wid  = threadIdx.x >> 5;
    int deg  = (i < n) ? (g_ideg[i] - 1) : 0;

    // warp inclusive scan
    int v = deg;
#pragma unroll
    for (int off = 1; off < 32; off <<= 1) {
        int t = __shfl_up_sync(0xffffffffu, v, off);
        if (lane >= off) v += t;
    }
    if (lane == 31) warp_sums[wid] = v;
    __syncthreads();
    if (wid == 0) {
        int s = (lane < 8) ? warp_sums[lane] : 0;
#pragma unroll
        for (int off = 1; off < 8; off <<= 1) {
            int t = __shfl_up_sync(0xffffffffu, s, off);
            if (lane >= off) s += t;
        }
        if (lane < 8) warp_sums[lane] = s;          // inclusive warp totals
        if (lane == 7) block_base = atomicAdd(&g_alloc_ctr, s);
    }
    __syncthreads();
    int base = block_base + ((wid > 0) ? warp_sums[wid - 1] : 0) + (v - deg);
    if (i < n) { g_row_beg[i] = base; g_fill[i] = base; }
}

__global__ void k_scatter(const int* __restrict__ src, const int* __restrict__ dst, int E) {
    int i = blockIdx.x * blockDim.x + threadIdx.x;
    int st = gridDim.x * blockDim.x;
    for (; i < E; i += st) {
        int d = dst[i];
        int pos = atomicAdd(&g_fill[d], 1);
        g_csr_src[pos] = src[i];
    }
}

// ---------------- fused GEMM ----------------
//   MODE 0: X_eff[r][k] = X[r][k] * out_norm[r]                      (layer 1, X = feat)
//   MODE 1: X_eff[r][k] = relu(g_AGG[r][k]*in_norm[r] + bprev[k]) * out_norm[r]
// Writes H only (self-loop handled in the aggregator's accumulator init).
template <int DOUT, int MODE>
__global__ void __launch_bounds__(256)
k_gemm(const float* __restrict__ X, const float* __restrict__ W,
       const float* __restrict__ bprev, int n)
{
    constexpr int CG   = DOUT / 4;    // float4 column groups
    constexpr int TY   = 256 / CG;    // row groups
    constexpr int ROWS = TY * 8;      // rows per block tile
    constexpr int XSS  = 136;         // xs row stride (floats)

    extern __shared__ float sm[];
    float* ws = sm;                   // [128][DOUT]
    float* xs = sm + 128 * DOUT;      // [ROWS][XSS]

    const int t    = threadIdx.x;
    const int row0 = blockIdx.x * ROWS;

    // stage W: all 128 K-rows x CG float4 column groups
    {
        const float4* W4  = (const float4*)W;
        float4*       ws4 = (float4*)ws;
        for (int i = t; i < 128 * CG; i += 256) ws4[i] = W4[i];
    }

    // stage X tile (previous layer's epilogue fused here)
    for (int i = t; i < ROWS * 32; i += 256) {
        int r  = i >> 5;
        int k4 = i & 31;
        int row = row0 + r;
        float4 v = make_float4(0.f, 0.f, 0.f, 0.f);
        if (row < n) {
            if (MODE == 0) {
                float on = g_out_norm[row];
                v = ((const float4*)X)[(size_t)row * 32 + k4];
                v.x *= on; v.y *= on; v.z *= on; v.w *= on;
            } else {
                float inn = g_in_norm[row];
                float on  = g_out_norm[row];
                float4 a  = ((const float4*)g_AGG)[(size_t)row * 32 + k4];
                float4 bb = ((const float4*)bprev)[k4];
                v.x = fmaxf(fmaf(a.x, inn, bb.x), 0.f) * on;
                v.y = fmaxf(fmaf(a.y, inn, bb.y), 0.f) * on;
                v.z = fmaxf(fmaf(a.z, inn, bb.z), 0.f) * on;
                v.w = fmaxf(fmaf(a.w, inn, bb.w), 0.f) * on;
            }
        }
        float* p = &xs[r * XSS + (k4 << 2)];
        p[0] = v.x; p[1] = v.y; p[2] = v.z; p[3] = v.w;
    }
    __syncthreads();

    const int tx = t % CG;
    const int ty = t / CG;
    float acc[8][4];
#pragma unroll
    for (int r = 0; r < 8; r++) { acc[r][0] = acc[r][1] = acc[r][2] = acc[r][3] = 0.f; }

    const float*  xrow = xs + ty * 8 * XSS;
    const float4* ws4  = (const float4*)ws;

#pragma unroll 4
    for (int k4 = 0; k4 < 32; k4++) {
        float4 w0 = ws4[(k4 * 4 + 0) * CG + tx];
        float4 w1 = ws4[(k4 * 4 + 1) * CG + tx];
        float4 w2 = ws4[(k4 * 4 + 2) * CG + tx];
        float4 w3 = ws4[(k4 * 4 + 3) * CG + tx];
#pragma unroll
        for (int r = 0; r < 8; r++) {
            float4 xv = *(const float4*)&xrow[r * XSS + k4 * 4];
            acc[r][0] = fmaf(xv.x, w0.x, acc[r][0]);
            acc[r][1] = fmaf(xv.x, w0.y, acc[r][1]);
            acc[r][2] = fmaf(xv.x, w0.z, acc[r][2]);
            acc[r][3] = fmaf(xv.x, w0.w, acc[r][3]);
            acc[r][0] = fmaf(xv.y, w1.x, acc[r][0]);
            acc[r][1] = fmaf(xv.y, w1.y, acc[r][1]);
            acc[r][2] = fmaf(xv.y, w1.z, acc[r][2]);
            acc[r][3] = fmaf(xv.y, w1.w, acc[r][3]);
            acc[r][0] = fmaf(xv.z, w2.x, acc[r][0]);
            acc[r][1] = fmaf(xv.z, w2.y, acc[r][1]);
            acc[r][2] = fmaf(xv.z, w2.z, acc[r][2]);
            acc[r][3] = fmaf(xv.z, w2.w, acc[r][3]);
            acc[r][0] = fmaf(xv.w, w3.x, acc[r][0]);
            acc[r][1] = fmaf(xv.w, w3.y, acc[r][1]);
            acc[r][2] = fmaf(xv.w, w3.z, acc[r][2]);
            acc[r][3] = fmaf(xv.w, w3.w, acc[r][3]);
        }
    }

#pragma unroll
    for (int r = 0; r < 8; r++) {
        int row = row0 + ty * 8 + r;
        if (row < n) {
            float4 v = make_float4(acc[r][0], acc[r][1], acc[r][2], acc[r][3]);
            ((float4*)g_H)[(size_t)row * CG + tx] = v;
        }
    }
}

// ---------------- CSR gather-reduce aggregation ----------------
// 128-wide: one warp per dst node; acc initialized with self-loop message H[dst].
__global__ void __launch_bounds__(256)
k_agg128(int n) {
    int w    = (blockIdx.x * blockDim.x + threadIdx.x) >> 5;
    int lane = threadIdx.x & 31;
    if (w >= n) return;
    const float4* H4 = (const float4*)g_H;
    int beg = g_row_beg[w];
    int end = beg + g_ideg[w] - 1;
    float4 acc = H4[(size_t)w * 32 + lane];   // self-loop
    int j = beg;
    for (; j + 1 < end; j += 2) {
        int s0 = __ldg(&g_csr_src[j]);
        int s1 = __ldg(&g_csr_src[j + 1]);
        float4 v0 = H4[(size_t)s0 * 32 + lane];
        float4 v1 = H4[(size_t)s1 * 32 + lane];
        acc.x += v0.x; acc.y += v0.y; acc.z += v0.z; acc.w += v0.w;
        acc.x += v1.x; acc.y += v1.y; acc.z += v1.z; acc.w += v1.w;
    }
    if (j < end) {
        int s0 = __ldg(&g_csr_src[j]);
        float4 v0 = H4[(size_t)s0 * 32 + lane];
        acc.x += v0.x; acc.y += v0.y; acc.z += v0.z; acc.w += v0.w;
    }
    ((float4*)g_AGG)[(size_t)w * 32 + lane] = acc;
}

// 64-wide, final layer: half-warp per dst node; fuses out = acc*in_norm + b3.
__global__ void __launch_bounds__(256)
k_agg64_final(const float* __restrict__ b3, float* __restrict__ out, int n) {
    int gt   = blockIdx.x * blockDim.x + threadIdx.x;
    int lane = gt & 31;
    int w    = gt >> 5;
    int sub  = lane >> 4;
    int l16  = lane & 15;
    int node = w * 2 + sub;
    if (node >= n) return;
    const float4* H4 = (const float4*)g_H;
    int beg = g_row_beg[node];
    int end = beg + g_ideg[node] - 1;
    float4 acc = H4[(size_t)node * 16 + l16];  // self-loop
    int j = beg;
    for (; j + 1 < end; j += 2) {
        int s0 = __ldg(&g_csr_src[j]);
        int s1 = __ldg(&g_csr_src[j + 1]);
        float4 v0 = H4[(size_t)s0 * 16 + l16];
        float4 v1 = H4[(size_t)s1 * 16 + l16];
        acc.x += v0.x; acc.y += v0.y; acc.z += v0.z; acc.w += v0.w;
        acc.x += v1.x; acc.y += v1.y; acc.z += v1.z; acc.w += v1.w;
    }
    if (j < end) {
        int s0 = __ldg(&g_csr_src[j]);
        float4 v0 = H4[(size_t)s0 * 16 + l16];
        acc.x += v0.x; acc.y += v0.y; acc.z += v0.z; acc.w += v0.w;
    }
    float inn = g_in_norm[node];
    float4 bb = ((const float4*)b3)[l16];
    float4 o;
    o.x = fmaf(acc.x, inn, bb.x);
    o.y = fmaf(acc.y, inn, bb.y);
    o.z = fmaf(acc.z, inn, bb.z);
    o.w = fmaf(acc.w, inn, bb.w);
    ((float4*)out)[(size_t)node * 16 + l16] = o;
}

// ---------------- launcher ----------------
extern "C" void kernel_launch(void* const* d_in, const int* in_sizes, int n_in,
                              void* d_out, int out_size)
{
    const float* feat = (const float*)d_in[0];
    const int*   src  = (const int*)d_in[1];
    const int*   dst  = (const int*)d_in[2];
    const float* W1   = (const float*)d_in[3];
    const float* b1   = (const float*)d_in[4];
    const float* W2   = (const float*)d_in[5];
    const float* b2   = (const float*)d_in[6];
    const float* W3   = (const float*)d_in[7];
    const float* b3   = (const float*)d_in[8];
    float*       out  = (float*)d_out;

    const int n = in_sizes[0] / 128;   // 100000
    const int E = in_sizes[1];         // 1600000

    const int smem128 = (128 * 128 + 64 * 136) * (int)sizeof(float);
    const int smem64  = (128 * 64 + 128 * 136) * (int)sizeof(float);
    cudaFuncSetAttribute((const void*)k_gemm<128, 0>,
                         cudaFuncAttributeMaxDynamicSharedMemorySize, smem128);
    cudaFuncSetAttribute((const void*)k_gemm<128, 1>,
                         cudaFuncAttributeMaxDynamicSharedMemorySize, smem128);
    cudaFuncSetAttribute((const void*)k_gemm<64, 1>,
                         cudaFuncAttributeMaxDynamicSharedMemorySize, smem64);

    // degrees + norms (self-loop via init=1)
    k_init_deg<<<(n + 255) / 256, 256>>>(n);
    k_count_deg<<<1024, 256>>>(src, dst, E);
    k_norms<<<(n + 255) / 256, 256>>>(n);

    // CSR build: parallel segment allocation + scatter (reused by all 3 layers)
    k_alloc<<<(n + 255) / 256, 256>>>(n);
    k_scatter<<<1024, 256>>>(src, dst, E);

    // layer 1
    k_gemm<128, 0><<<(n + 63) / 64, 256, smem128>>>(feat, W1, nullptr, n);
    k_agg128<<<(n * 32 + 255) / 256, 256>>>(n);

    // layer 2
    k_gemm<128, 1><<<(n + 63) / 64, 256, smem128>>>(nullptr, W2, b1, n);
    k_agg128<<<(n * 32 + 255) / 256, 256>>>(n);

    // layer 3 (64-wide) + fused final epilogue straight to d_out
    k_gemm<64, 1><<<(n + 127) / 128, 256, smem64>>>(nullptr, W3, b2, n);
    k_agg64_final<<<(n * 16 + 255) / 256, 256>>>(b3, out, n);
}